// round 1
// baseline (speedup 1.0000x reference)
#include <cuda_runtime.h>

#define NN      51
#define HIDN    64
#define HEADS   4
#define DTOT    256     // HEADS*HIDN
#define OUTG    128
#define LH      32
#define NC      8
#define BBATCH  256
#define FFEAT   50
#define GG      (BBATCH*FFEAT)   // 12800
#define SLOPEF  0.01f

// ---------------- scratch (no allocs allowed) ----------------
__device__ float d_u[HEADS][4];          // usrc0, usrc1, udst0, udst1
__device__ float d_vs[DTOT];             // W2^T @ a2[:128]
__device__ float d_vd[DTOT];             // W2^T @ a2[128:]
__device__ float d_wb[DTOT];             // mean_o W2[o,:]
__device__ float d_WihT0[NN * OUTG];     // transposed Wih0: [n][gate]
__device__ float d_b0[OUTG];
__device__ float d_b1[OUTG];
__device__ float d_xp0[GG * OUTG];       // LSTM layer0 gate pre-activations
__device__ float d_hseq[BBATCH * FFEAT * LH]; // layer1 hidden outputs

// ---------------- helpers ----------------
__device__ __forceinline__ float fsig(float x) {
    return 1.0f / (1.0f + __expf(-x));
}
__device__ __forceinline__ float ftanhf(float x) {
    float e = __expf(-2.0f * fabsf(x));
    float r = __fdividef(1.0f - e, 1.0f + e);
    return copysignf(r, x);
}

// ---------------- kernel A: tiny precompute ----------------
__global__ void prep_kernel(const float* __restrict__ W1, const float* __restrict__ a1,
                            const float* __restrict__ W2, const float* __restrict__ a2,
                            const float* __restrict__ Wih0,
                            const float* __restrict__ bih0, const float* __restrict__ bhh0,
                            const float* __restrict__ bih1, const float* __restrict__ bhh1) {
    int t = threadIdx.x; // 256 threads
    // v_src, v_dst, w2bar  (thread t = feature dim d)
    {
        float vs = 0.f, vd = 0.f, wb = 0.f;
        for (int o = 0; o < OUTG; o++) {
            float w = W2[o * DTOT + t];
            vs += w * a2[o];
            vd += w * a2[OUTG + o];
            wb += w;
        }
        d_vs[t] = vs; d_vd[t] = vd; d_wb[t] = wb * (1.0f / OUTG);
    }
    // u[h][which]: which = side*2 + c   (side 0 = src, 1 = dst)
    if (t < HEADS * 4) {
        int h = t >> 2, which = t & 3;
        int c = which & 1, side = which >> 1;
        float s = 0.f;
        for (int o = 0; o < HIDN; o++)
            s += W1[(h * HIDN + o) * 2 + c] * a1[h * 2 * HIDN + side * HIDN + o];
        d_u[h][which] = s;
    }
    // transpose Wih0 -> [n][gate]
    for (int idx = t; idx < NN * OUTG; idx += 256) {
        int n = idx / OUTG, g = idx % OUTG;
        d_WihT0[idx] = Wih0[g * NN + n];
    }
    if (t < OUTG) {
        d_b0[t] = bih0[t] + bhh0[t];
        d_b1[t] = bih1[t] + bhh1[t];
    }
}

// ---------------- kernel B: fused GAT (both layers) + LSTM0 input proj ----------------
__global__ void __launch_bounds__(256) gat_kernel(const float* __restrict__ feat,
                                                  const float* __restrict__ W1g) {
    __shared__ float2 xv[NN];             // node features
    __shared__ float  W1s[DTOT * 2];      // W1 flattened [d][c]
    __shared__ float  vs_s[DTOT], vd_s[DTOT], wb_s[DTOT];
    __shared__ float2 PR[HEADS][NN];      // exp(es), exp(.01 es)
    __shared__ float2 QS[HEADS][NN];      // exp(ed), exp(.01 ed)
    __shared__ float2 ssm[HEADS][NN];     // attention-weighted s0, s1
    __shared__ float2 P2[NN];             // exp(es2), exp(.01 es2)
    __shared__ float2 Q2[NN];             // exp(ed2), exp(.01 ed2)
    __shared__ float  zb[NN];             // zbar
    __shared__ float  exts[NN];           // extracted row

    int g = blockIdx.x;
    int t = threadIdx.x;

    // ---- stage 0: loads ----
    {
        const float2* x2 = reinterpret_cast<const float2*>(feat + (size_t)g * (NN * 2));
        if (t < NN) xv[t] = x2[t];
        for (int i = t; i < DTOT * 2; i += 256) W1s[i] = W1g[i];
        if (t < DTOT) { vs_s[t] = d_vs[t]; vd_s[t] = d_vd[t]; wb_s[t] = d_wb[t]; }
    }
    __syncthreads();

    // ---- stage 1: GAT1 logits + exps (204 tasks) ----
    if (t < HEADS * NN) {
        int h = t / NN, n = t % NN;
        float u0 = d_u[h][0], u1 = d_u[h][1], u2 = d_u[h][2], u3 = d_u[h][3];
        float2 xn = xv[n];
        float es = xn.x * u0 + xn.y * u1;
        float ed = xn.x * u2 + xn.y * u3;
        PR[h][n] = make_float2(__expf(es), __expf(SLOPEF * es));
        QS[h][n] = make_float2(__expf(ed), __expf(SLOPEF * ed));
    }
    __syncthreads();

    // ---- stage 2: GAT1 attention-weighted feature sums (204 tasks, 51-loop) ----
    if (t < HEADS * NN) {
        int h = t / NN, j = t % NN;
        float2 q = QS[h][j];
        float den = 0.f, s0 = 0.f, s1 = 0.f;
#pragma unroll 3
        for (int i = 0; i < NN; i++) {
            float2 pr = PR[h][i];
            float w = fmaxf(pr.x * q.x, pr.y * q.y);   // exp(leaky(es_i+ed_j))
            float2 xi = xv[i];
            den += w; s0 += w * xi.x; s1 += w * xi.y;
        }
        // remove diagonal (i == j)
        {
            float2 pr = PR[h][j];
            float w = fmaxf(pr.x * q.x, pr.y * q.y);
            float2 xj = xv[j];
            den -= w; s0 -= w * xj.x; s1 -= w * xj.y;
        }
        float inv = __fdividef(1.0f, den);
        ssm[h][j] = make_float2(s0 * inv, s1 * inv);
    }
    __syncthreads();

    // ---- stage 3: elu(h1) projections -> es2, ed2, zbar (warp per j) ----
    {
        int wid = t >> 5, lane = t & 31;
        float w10[8], w11[8], vsr[8], vdr[8], wbr[8];
#pragma unroll
        for (int k = 0; k < 8; k++) {
            int d = k * 32 + lane;
            w10[k] = W1s[2 * d]; w11[k] = W1s[2 * d + 1];
            vsr[k] = vs_s[d]; vdr[k] = vd_s[d]; wbr[k] = wb_s[d];
        }
        for (int j = wid; j < NN; j += 8) {
            float s[8];
#pragma unroll
            for (int h = 0; h < 4; h++) {
                float2 sv = ssm[h][j];
                s[2 * h] = sv.x; s[2 * h + 1] = sv.y;
            }
            float a_es = 0.f, a_ed = 0.f, a_zb = 0.f;
#pragma unroll
            for (int k = 0; k < 8; k++) {
                int h = k >> 1;
                float h1 = s[2 * h] * w10[k] + s[2 * h + 1] * w11[k];
                float em1 = __expf(h1) - 1.0f;
                float he = (h1 > 0.f) ? h1 : em1;      // elu
                a_es += he * vsr[k]; a_ed += he * vdr[k]; a_zb += he * wbr[k];
            }
#pragma unroll
            for (int off = 16; off; off >>= 1) {
                a_es += __shfl_down_sync(0xffffffffu, a_es, off);
                a_ed += __shfl_down_sync(0xffffffffu, a_ed, off);
                a_zb += __shfl_down_sync(0xffffffffu, a_zb, off);
            }
            if (lane == 0) {
                P2[j] = make_float2(__expf(a_es), __expf(SLOPEF * a_es));
                Q2[j] = make_float2(__expf(a_ed), __expf(SLOPEF * a_ed));
                zb[j] = a_zb;
            }
        }
    }
    __syncthreads();

    // ---- stage 5: GAT2 attention -> extracted (51 tasks) ----
    if (t < NN) {
        float2 q = Q2[t];
        float den = 0.f, acc = 0.f;
#pragma unroll 3
        for (int i = 0; i < NN; i++) {
            float2 p = P2[i];
            float w = fmaxf(p.x * q.x, p.y * q.y);
            den += w; acc += w * zb[i];
        }
        {
            float2 p = P2[t];
            float w = fmaxf(p.x * q.x, p.y * q.y);
            den -= w; acc -= w * zb[t];
        }
        exts[t] = acc * __fdividef(1.0f, den);
    }
    __syncthreads();

    // ---- stage 6: LSTM layer0 input projection (fused) ----
    if (t < OUTG) {
        float acc = d_b0[t];
#pragma unroll 3
        for (int n = 0; n < NN; n++)
            acc += exts[n] * d_WihT0[n * OUTG + t];
        d_xp0[(size_t)g * OUTG + t] = acc;
    }
}

// ---------------- kernel C: pipelined 2-layer LSTM recurrence ----------------
__global__ void __launch_bounds__(256) lstm_kernel(const float* __restrict__ Whh0,
                                                   const float* __restrict__ Wih1,
                                                   const float* __restrict__ Whh1) {
    __shared__ float h0[LH], h1s[LH], g0[OUTG], g1[OUTG];
    int f = blockIdx.x;    // 50 blocks
    int t = threadIdx.x;   // 256 threads

    float wa[32], wbv[32];
    if (t < OUTG) {
#pragma unroll
        for (int k = 0; k < 32; k++) wa[k] = Whh0[t * 32 + k];
    } else {
        int r = t - OUTG;
#pragma unroll
        for (int k = 0; k < 32; k++) { wa[k] = Wih1[r * 32 + k]; wbv[k] = Whh1[r * 32 + k]; }
    }
    float b1v = (t >= OUTG) ? d_b1[t - OUTG] : 0.f;
    float c_ = 0.f;
    if (t < LH) { h0[t] = 0.f; h1s[t] = 0.f; }
    __syncthreads();

    for (int k = 0; k <= BBATCH; k++) {
        // phase A: gate pre-activations (layer0 @ time k, layer1 @ time k-1)
        if (t < OUTG) {
            if (k < BBATCH) {
                float acc = d_xp0[((size_t)k * FFEAT + f) * OUTG + t];
                float a0 = 0.f, a1_ = 0.f, a2_ = 0.f, a3 = 0.f;
#pragma unroll
                for (int j = 0; j < 32; j += 4) {
                    a0 += wa[j] * h0[j];
                    a1_ += wa[j + 1] * h0[j + 1];
                    a2_ += wa[j + 2] * h0[j + 2];
                    a3 += wa[j + 3] * h0[j + 3];
                }
                g0[t] = acc + ((a0 + a1_) + (a2_ + a3));
            }
        } else if (k >= 1) {
            int r = t - OUTG;
            float a0 = 0.f, a1_ = 0.f, a2_ = 0.f, a3 = 0.f;
#pragma unroll
            for (int j = 0; j < 32; j += 4) {
                a0 += wa[j] * h0[j] + wbv[j] * h1s[j];
                a1_ += wa[j + 1] * h0[j + 1] + wbv[j + 1] * h1s[j + 1];
                a2_ += wa[j + 2] * h0[j + 2] + wbv[j + 2] * h1s[j + 2];
                a3 += wa[j + 3] * h0[j + 3] + wbv[j + 3] * h1s[j + 3];
            }
            g1[r] = b1v + ((a0 + a1_) + (a2_ + a3));
        }
        __syncthreads();
        // phase B: state updates
        if (t < 32) {
            if (k < BBATCH) {
                float gi = g0[t], gf = g0[32 + t], gg = g0[64 + t], go = g0[96 + t];
                c_ = fsig(gf) * c_ + fsig(gi) * ftanhf(gg);
                h0[t] = fsig(go) * ftanhf(c_);
            }
        } else if (t < 64 && k >= 1) {
            int r = t - 32;
            float gi = g1[r], gf = g1[32 + r], gg = g1[64 + r], go = g1[96 + r];
            c_ = fsig(gf) * c_ + fsig(gi) * ftanhf(gg);
            float hn = fsig(go) * ftanhf(c_);
            h1s[r] = hn;
            d_hseq[(((size_t)(k - 1)) * FFEAT + f) * LH + r] = hn;
        }
        __syncthreads();
    }
}

// ---------------- kernel D: final FC ----------------
__global__ void __launch_bounds__(256) fc_kernel(const float* __restrict__ Wfc,
                                                 const float* __restrict__ bfc,
                                                 float* __restrict__ out) {
    int b = blockIdx.x;          // 256 blocks
    int t = threadIdx.x;
    int k = t >> 5, lane = t & 31;   // 8 warps = 8 classes
    const float* y = d_hseq + (size_t)b * (FFEAT * LH);
    const float* w = Wfc + (size_t)k * (FFEAT * LH);
    float acc = 0.f;
    for (int i = lane; i < FFEAT * LH; i += 32)
        acc += y[i] * w[i];
#pragma unroll
    for (int off = 16; off; off >>= 1)
        acc += __shfl_down_sync(0xffffffffu, acc, off);
    if (lane == 0) out[b * NC + k] = acc + bfc[k];
}

// ---------------- launch ----------------
extern "C" void kernel_launch(void* const* d_in, const int* in_sizes, int n_in,
                              void* d_out, int out_size) {
    const float* feat = (const float*)d_in[0];
    const float* W1   = (const float*)d_in[1];
    const float* a1   = (const float*)d_in[2];
    const float* W2   = (const float*)d_in[3];
    const float* a2   = (const float*)d_in[4];
    const float* Wih0 = (const float*)d_in[5];
    const float* Whh0 = (const float*)d_in[6];
    const float* bih0 = (const float*)d_in[7];
    const float* bhh0 = (const float*)d_in[8];
    const float* Wih1 = (const float*)d_in[9];
    const float* Whh1 = (const float*)d_in[10];
    const float* bih1 = (const float*)d_in[11];
    const float* bhh1 = (const float*)d_in[12];
    const float* Wfc  = (const float*)d_in[13];
    const float* bfc  = (const float*)d_in[14];
    float* out = (float*)d_out;

    prep_kernel<<<1, 256>>>(W1, a1, W2, a2, Wih0, bih0, bhh0, bih1, bhh1);
    gat_kernel<<<GG, 256>>>(feat, W1);
    lstm_kernel<<<FFEAT, 256>>>(Whh0, Wih1, Whh1);
    fc_kernel<<<BBATCH, 256>>>(Wfc, bfc, out);
}